// round 3
// baseline (speedup 1.0000x reference)
#include <cuda_runtime.h>
#include <cuda_bf16.h>

// Problem constants (SwitchingGRU1: B=256, T=512, H=128, S=8, N_SWITCH=6)
#define BB   256
#define TT   512
#define HH   128
#define SS   8
#define NSW  6

// Swizzled weight scratch: 18 matrices of 128x128 fp32 = 1.18 MB.
// Layout per matrix m = g*NSW + s (g: 0=r,1=z,2=n):
//   dst[m*16384 + (j>>2)*512 + i*4 + (j&3)] = W_g[s][i][j]
// so thread i reads float4 {W[i][4jb..4jb+3]} at float4-index (jb*128 + i):
// consecutive threads -> consecutive 16B -> fully coalesced 512B/warp.
__device__ float g_wswz[3 * NSW * HH * HH];

__global__ void swz_kernel(const float* __restrict__ Wr,
                           const float* __restrict__ Wz,
                           const float* __restrict__ Wn) {
    int idx = blockIdx.x * blockDim.x + threadIdx.x;
    if (idx >= 3 * NSW * HH * HH) return;
    int m = idx >> 14;          // matrix id 0..17
    int r = idx & 16383;
    int i = r >> 7;             // row (output)
    int j = r & 127;            // col (input)
    int g = m / NSW;
    int s = m % NSW;
    const float* W = (g == 0) ? Wr : (g == 1) ? Wz : Wn;
    float v = W[s * HH * HH + i * HH + j];
    g_wswz[m * HH * HH + (j >> 2) * (4 * HH) + i * 4 + (j & 3)] = v;
}

__global__ __launch_bounds__(HH) void gru_kernel(
    const float* __restrict__ stim,     // [B,T,S]
    const int*   __restrict__ swid,     // [B,T]
    const float* __restrict__ mask,     // [B,T]
    const float* __restrict__ Win,      // [3H,S]
    const float* __restrict__ bin_,     // [3H]
    const float* __restrict__ bhr,      // [NSW,H]
    const float* __restrict__ bhz,      // [NSW,H]
    const float* __restrict__ bhn,      // [NSW,H]
    const float* __restrict__ Wo,       // [2,H]
    const float* __restrict__ bo,       // [2]
    float*       __restrict__ out)      // [B,T,2]
{
    __shared__ __align__(16) float h_sh[HH];
    __shared__ float winT[SS * 3 * HH];   // [s][o] transposed input projection
    __shared__ float red[8];              // 4 warps x 2 logits

    const int b   = blockIdx.x;
    const int tid = threadIdx.x;

    // Stage Win transposed: winT[s][o] = Win[o][s]  (conflict-free reads later)
    for (int e = tid; e < 3 * HH * SS; e += HH) {
        int o = e >> 3, s = e & 7;
        winT[s * (3 * HH) + o] = Win[e];
    }

    // Hoist per-thread constants
    const float bi0 = bin_[tid];
    const float bi1 = bin_[HH + tid];
    const float bi2 = bin_[2 * HH + tid];
    const float wo0 = Wo[tid];
    const float wo1 = Wo[HH + tid];
    const float bo0 = __ldg(bo);
    const float bo1 = __ldg(bo + 1);
    float bhr_r[NSW], bhz_r[NSW], bhn_r[NSW];
#pragma unroll
    for (int s = 0; s < NSW; s++) {
        bhr_r[s] = bhr[s * HH + tid];
        bhz_r[s] = bhz[s * HH + tid];
        bhn_r[s] = bhn[s * HH + tid];
    }

    float h = 0.0f;
    h_sh[tid] = 0.0f;
    __syncthreads();

    const float4* __restrict__ Wbase = (const float4*)g_wswz;
    const float*  __restrict__ stim_b = stim + (size_t)b * TT * SS;
    const int*    __restrict__ sid_b  = swid + (size_t)b * TT;
    const float*  __restrict__ mask_b = mask + (size_t)b * TT;
    float*        __restrict__ out_b  = out  + (size_t)b * TT * 2;

    for (int t = 0; t < TT; t++) {
        // ---- input projection x = Win @ stim[b,t] + bin ----
        const float4* st4 = (const float4*)(stim_b + t * SS);
        float4 sa = __ldg(st4);
        float4 sb = __ldg(st4 + 1);
        float sv[8] = {sa.x, sa.y, sa.z, sa.w, sb.x, sb.y, sb.z, sb.w};
        float xr = bi0, xz = bi1, xn = bi2;
#pragma unroll
        for (int s = 0; s < 8; s++) {
            xr += winT[s * 384 + tid]            * sv[s];
            xz += winT[s * 384 + HH + tid]       * sv[s];
            xn += winT[s * 384 + 2 * HH + tid]   * sv[s];
        }

        // ---- recurrent matvecs (weights streamed from L2, coalesced) ----
        int sid = sid_b[t];
        sid = min(max(sid, 0), NSW - 1);
        const float4* __restrict__ WR = Wbase + (size_t)(0 * NSW + sid) * 4096;
        const float4* __restrict__ WZ = Wbase + (size_t)(1 * NSW + sid) * 4096;
        const float4* __restrict__ WN = Wbase + (size_t)(2 * NSW + sid) * 4096;
        float hr = bhr_r[sid], hz = bhz_r[sid], hn = bhn_r[sid];
        const float4* h4 = (const float4*)h_sh;
#pragma unroll 8
        for (int jb = 0; jb < 32; jb++) {
            float4 hv = h4[jb];
            float4 wr = __ldg(WR + jb * HH + tid);
            float4 wz = __ldg(WZ + jb * HH + tid);
            float4 wn = __ldg(WN + jb * HH + tid);
            hr += wr.x * hv.x + wr.y * hv.y + wr.z * hv.z + wr.w * hv.w;
            hz += wz.x * hv.x + wz.y * hv.y + wz.z * hv.z + wz.w * hv.w;
            hn += wn.x * hv.x + wn.y * hv.y + wn.z * hv.z + wn.w * hv.w;
        }

        // ---- gates ----
        float r = 1.0f / (1.0f + expf(-(xr + hr)));
        float z = 1.0f / (1.0f + expf(-(xz + hz)));
        float n = tanhf(xn + r * hn);
        float hnew = (1.0f - z) * n + z * h;
        float m = mask_b[t];
        h = m * hnew + (1.0f - m) * h;

        // ---- logits: 2 dot products over H, warp-shuffle reduce ----
        float p0 = wo0 * h;
        float p1 = wo1 * h;
#pragma unroll
        for (int o = 16; o; o >>= 1) {
            p0 += __shfl_down_sync(0xffffffffu, p0, o);
            p1 += __shfl_down_sync(0xffffffffu, p1, o);
        }

        __syncthreads();                 // all threads done reading h_sh(t-1)
        h_sh[tid] = h;
        if ((tid & 31) == 0) {
            red[tid >> 5]     = p0;
            red[4 + (tid >> 5)] = p1;
        }
        __syncthreads();                 // h_sh(t) and partials visible
        if (tid == 0) out_b[2 * t]     = red[0] + red[1] + red[2] + red[3] + bo0;
        if (tid == 1) out_b[2 * t + 1] = red[4] + red[5] + red[6] + red[7] + bo1;
    }
}

extern "C" void kernel_launch(void* const* d_in, const int* in_sizes, int n_in,
                              void* d_out, int out_size) {
    const float* stim  = (const float*)d_in[0];
    const int*   swid  = (const int*)  d_in[1];
    const float* mask  = (const float*)d_in[2];
    const float* Win   = (const float*)d_in[3];
    const float* bin_  = (const float*)d_in[4];
    const float* W_hr  = (const float*)d_in[5];
    const float* W_hz  = (const float*)d_in[6];
    const float* W_hn  = (const float*)d_in[7];
    const float* b_hr  = (const float*)d_in[8];
    const float* b_hz  = (const float*)d_in[9];
    const float* b_hn  = (const float*)d_in[10];
    const float* Wo    = (const float*)d_in[11];
    const float* bo    = (const float*)d_in[12];
    float* out = (float*)d_out;

    const int total = 3 * NSW * HH * HH;
    swz_kernel<<<(total + 255) / 256, 256>>>(W_hr, W_hz, W_hn);
    gru_kernel<<<BB, HH>>>(stim, swid, mask, Win, bin_, b_hr, b_hz, b_hn,
                           Wo, bo, out);
}

// round 5
// speedup vs baseline: 1.8223x; 1.8223x over previous
#include <cuda_runtime.h>
#include <cuda_bf16.h>

// Problem constants (SwitchingGRU1: B=256, T=512, H=128, S=8, N_SWITCH=6)
#define BB   256
#define TT   512
#define HH   128
#define SS   8
#define NSW  6

// Swizzled weight scratch: 18 matrices of 128x128 fp32 = 1.18 MB.
// Layout per matrix m = g*NSW + s (g: 0=r,1=z,2=n):
//   dst[m*16384 + (j>>2)*512 + i*4 + (j&3)] = W_g[s][i][j]
// so thread i reads float4 {W[i][4jb..4jb+3]} at float4-index (jb*128 + i):
// consecutive lanes -> consecutive 16B -> fully coalesced 512B/warp.
__device__ float g_wswz[3 * NSW * HH * HH];

__global__ void swz_kernel(const float* __restrict__ Wr,
                           const float* __restrict__ Wz,
                           const float* __restrict__ Wn) {
    int idx = blockIdx.x * blockDim.x + threadIdx.x;
    if (idx >= 3 * NSW * HH * HH) return;
    int m = idx >> 14;          // matrix id 0..17
    int r = idx & 16383;
    int i = r >> 7;             // row (output)
    int j = r & 127;            // col (input)
    int g = m / NSW;
    int s = m % NSW;
    const float* W = (g == 0) ? Wr : (g == 1) ? Wz : Wn;
    float v = W[s * HH * HH + i * HH + j];
    g_wswz[m * HH * HH + (j >> 2) * (4 * HH) + i * 4 + (j & 3)] = v;
}

// 384 threads: thread (g = tid>>7, i = tid&127) owns gate g, row i.
__global__ __launch_bounds__(384, 2) void gru_kernel(
    const float* __restrict__ stim,     // [B,T,S]
    const int*   __restrict__ swid,     // [B,T]
    const float* __restrict__ mask,     // [B,T]
    const float* __restrict__ Win,      // [3H,S]
    const float* __restrict__ bin_,     // [3H]
    const float* __restrict__ bhr,      // [NSW,H]
    const float* __restrict__ bhz,      // [NSW,H]
    const float* __restrict__ bhn,      // [NSW,H]
    const float* __restrict__ Wo,       // [2,H]
    const float* __restrict__ bo,       // [2]
    float*       __restrict__ out)      // [B,T,2]
{
    __shared__ __align__(16) float h_sh[HH];
    __shared__ float gz[HH];              // z pre-activation (gate 1)
    __shared__ float gn[HH];              // recurrent part of n (gate 2)
    __shared__ float gxn[HH];             // input part of n (gate 2)
    __shared__ float red[8];              // 4 warps x 2 logit partials
    __shared__ __align__(16) float stim_sm[TT * SS];   // 16 KB
    __shared__ int   sid_sm[TT];
    __shared__ float mask_sm[TT];

    const int b   = blockIdx.x;
    const int tid = threadIdx.x;
    const int g   = tid >> 7;     // 0=r, 1=z, 2=n
    const int i   = tid & 127;    // row within gate

    // ---- one-time staging: full sequence of stim/sid/mask for this batch ----
    {
        const float4* st4 = (const float4*)(stim + (size_t)b * TT * SS);
        float4* ss4 = (float4*)stim_sm;
        for (int e = tid; e < TT * SS / 4; e += 384) ss4[e] = st4[e];
        const int*   sb = swid + (size_t)b * TT;
        const float* mb = mask + (size_t)b * TT;
        for (int e = tid; e < TT; e += 384) {
            int s = sb[e];
            sid_sm[e]  = min(max(s, 0), NSW - 1);
            mask_sm[e] = mb[e];
        }
    }

    // ---- per-thread constants in registers ----
    float wv[SS];
#pragma unroll
    for (int s = 0; s < SS; s++) wv[s] = Win[tid * SS + s];   // row tid of Win
    const float bi = bin_[tid];
    const float* bhp = (g == 0) ? bhr : (g == 1) ? bhz : bhn;
    float bh_r[NSW];
#pragma unroll
    for (int s = 0; s < NSW; s++) bh_r[s] = bhp[s * HH + i];
    const float wo0 = Wo[i];          // used by g==0 only
    const float wo1 = Wo[HH + i];
    const float bo0 = __ldg(bo);
    const float bo1 = __ldg(bo + 1);

    float hreg = 0.0f;                // live only in g==0 threads
    if (g == 0) h_sh[i] = 0.0f;
    __syncthreads();

    const float4* __restrict__ Wgate =
        (const float4*)g_wswz + (size_t)g * NSW * (HH * HH / 4);
    float* __restrict__ out_b = out + (size_t)b * TT * 2;

    for (int t = 0; t < TT; t++) {
        // ---- step t-1 logits: group 0 only, behind a NAMED barrier so
        //      groups 1/2 proceed straight to their weight loads ----
        if (g == 0 && t > 0) {
            float p0 = wo0 * hreg;
            float p1 = wo1 * hreg;
#pragma unroll
            for (int o = 16; o; o >>= 1) {
                p0 += __shfl_down_sync(0xffffffffu, p0, o);
                p1 += __shfl_down_sync(0xffffffffu, p1, o);
            }
            if ((tid & 31) == 0) { red[tid >> 5] = p0; red[4 + (tid >> 5)] = p1; }
            asm volatile("bar.sync 1, 128;" ::: "memory");
            if (tid == 0) out_b[2 * (t - 1)]     = red[0] + red[1] + red[2] + red[3] + bo0;
            if (tid == 1) out_b[2 * (t - 1) + 1] = red[4] + red[5] + red[6] + red[7] + bo1;
        }

        const int sid = sid_sm[t];

        // ---- input projection for this thread's gate row ----
        const float* sv = stim_sm + t * SS;
        float x = bi;
#pragma unroll
        for (int s = 0; s < SS; s++) x = fmaf(wv[s], sv[s], x);

        // ---- recurrent matvec: 32 independent coalesced LDG.128 ----
        float acc = bh_r[sid];
        const float4* __restrict__ W = Wgate + (size_t)sid * (HH * HH / 4) + i;
        const float4* h4 = (const float4*)h_sh;
#pragma unroll
        for (int jb = 0; jb < 32; jb++) {
            float4 w  = __ldg(W + jb * HH);
            float4 hv = h4[jb];
            acc = fmaf(w.x, hv.x, acc);
            acc = fmaf(w.y, hv.y, acc);
            acc = fmaf(w.z, hv.z, acc);
            acc = fmaf(w.w, hv.w, acc);
        }

        if (g == 1)      gz[i]  = x + acc;        // z pre-activation
        else if (g == 2) { gn[i] = acc; gxn[i] = x; }  // n: keep parts split
        __syncthreads();   // sync#1: gate results visible; h_sh reads done

        if (g == 0) {
            float r = 1.0f / (1.0f + expf(-(x + acc)));
            float z = 1.0f / (1.0f + expf(-gz[i]));
            float n = tanhf(gxn[i] + r * gn[i]);
            float hnew = n + z * (hreg - n);          // (1-z)*n + z*h
            float m = mask_sm[t];
            hreg = hreg + m * (hnew - hreg);          // m*hnew + (1-m)*h
            h_sh[i] = hreg;
        }
        __syncthreads();   // sync#2: h(t) visible for next step
    }

    // ---- final step's logits ----
    if (g == 0) {
        float p0 = wo0 * hreg;
        float p1 = wo1 * hreg;
#pragma unroll
        for (int o = 16; o; o >>= 1) {
            p0 += __shfl_down_sync(0xffffffffu, p0, o);
            p1 += __shfl_down_sync(0xffffffffu, p1, o);
        }
        if ((tid & 31) == 0) { red[tid >> 5] = p0; red[4 + (tid >> 5)] = p1; }
        asm volatile("bar.sync 1, 128;" ::: "memory");
        if (tid == 0) out_b[2 * (TT - 1)]     = red[0] + red[1] + red[2] + red[3] + bo0;
        if (tid == 1) out_b[2 * (TT - 1) + 1] = red[4] + red[5] + red[6] + red[7] + bo1;
    }
}

extern "C" void kernel_launch(void* const* d_in, const int* in_sizes, int n_in,
                              void* d_out, int out_size) {
    const float* stim  = (const float*)d_in[0];
    const int*   swid  = (const int*)  d_in[1];
    const float* mask  = (const float*)d_in[2];
    const float* Win   = (const float*)d_in[3];
    const float* bin_  = (const float*)d_in[4];
    const float* W_hr  = (const float*)d_in[5];
    const float* W_hz  = (const float*)d_in[6];
    const float* W_hn  = (const float*)d_in[7];
    const float* b_hr  = (const float*)d_in[8];
    const float* b_hz  = (const float*)d_in[9];
    const float* b_hn  = (const float*)d_in[10];
    const float* Wo    = (const float*)d_in[11];
    const float* bo    = (const float*)d_in[12];
    float* out = (float*)d_out;

    const int total = 3 * NSW * HH * HH;
    swz_kernel<<<(total + 255) / 256, 256>>>(W_hr, W_hz, W_hn);
    gru_kernel<<<BB, 384>>>(stim, swid, mask, Win, bin_, b_hr, b_hz, b_hn,
                            Wo, bo, out);
}